// round 15
// baseline (speedup 1.0000x reference)
#include <cuda_runtime.h>
#include <cuda_fp16.h>
#include <cstdint>
#include <float.h>

// AFM fused kernel — fp16 single-term mma.sync, warp-pair N-split:
// each tile is computed by TWO warps, each owning 32 of 64 hidden columns
// (bf 32 regs, acc 20 regs -> 3 CTAs/SM, occ 36%). Partial logits combine
// additively in the softmax phase (no mid-loop sync). 2 batches/CTA.
//
// out[b] = bl + sum_p softmax_p(l_p) * s_p
//   inner_p = rn16(x[b,r])∘rn16(x[b,c])   (f16x2 products = A fragments)
//   s_p = inner_p·rn16(Wl)                (extra m16n8k16, half-0 warps only)
//   l_p = W2·relu(W1·inner_p + b1)        (+b2 dropped: shift-invariant)

namespace {

constexpr int NF    = 40;
constexpr int ED    = 64;
constexpr int NPAIR = NF * (NF - 1) / 2;   // 780
constexpr int NTILE = (NPAIR + 15) / 16;   // 49
constexpr int NPAD  = NTILE * 16;          // 784
constexpr int NT    = 256;
constexpr int ST2   = 36;                  // sx2 row stride in u32 (half2) words

__device__ __forceinline__ uint32_t pack_h2(float v0, float v1) {
    const __half2 h = __floats2half2_rn(v0, v1);   // .x = v0 (low half)
    return *(const uint32_t*)&h;
}
__device__ __forceinline__ uint32_t h2mul(uint32_t a, uint32_t b) {
    uint32_t d;
    asm("mul.rn.f16x2 %0, %1, %2;" : "=r"(d) : "r"(a), "r"(b));
    return d;
}
__device__ __forceinline__ void mma16816(float* c, const uint32_t* a,
                                         uint32_t b0, uint32_t b1) {
    asm volatile(
        "mma.sync.aligned.m16n8k16.row.col.f32.f16.f16.f32 "
        "{%0,%1,%2,%3}, {%4,%5,%6,%7}, {%8,%9}, {%0,%1,%2,%3};"
        : "+f"(c[0]), "+f"(c[1]), "+f"(c[2]), "+f"(c[3])
        : "r"(a[0]), "r"(a[1]), "r"(a[2]), "r"(a[3]), "r"(b0), "r"(b1));
}

// pair index p -> (row<<8)|col for upper-triangle k=1, NF=40.
__device__ __forceinline__ uint32_t decode_pair(int p) {
    const float d = sqrtf(6241.0f - 8.0f * (float)p);
    int r = __float2int_rd((79.0f - d) * 0.5f);
    if (r * (79 - r) / 2 > p) --r;
    if ((r + 1) * (78 - r) / 2 <= p) ++r;
    const int c = p - r * (79 - r) / 2 + r + 1;
    return ((uint32_t)r << 8) | (uint32_t)c;
}

__global__ __launch_bounds__(NT, 3)
void afm_mma_kernel(const float* __restrict__ x,
                    const float* __restrict__ W1,
                    const float* __restrict__ b1,
                    const float* __restrict__ W2,
                    const float* __restrict__ b2,
                    const float* __restrict__ Wl,
                    const float* __restrict__ bl,
                    float* __restrict__ out)
{
    __shared__ __align__(8)  uint32_t sx2[2 * NF * ST2];  // rows 0-39: b0, 40-79: b1
    __shared__           uint32_t sW1h[ED][36];           // staging for B frag load
    __shared__ __align__(16) float4   sEpi[32];           // (b1,W2,b1,W2) per (n,t)
    __shared__           float    lpart[2][2 * NPAD];     // partial logits per half
    __shared__           float    svals[2 * NPAD];
    __shared__           float    red[24];
    __shared__           float    scal1[1];

    const int tid = threadIdx.x;
    const int wid = tid >> 5, lid = tid & 31;
    const int gid = lid >> 2, t = lid & 3;
    const int wp = wid >> 1, half = wid & 1;  // warp-pair id, N-half
    const int b = blockIdx.x;                 // handles batches 2b, 2b+1

    // ---- stage x for BOTH batches (contiguous in gmem) as half2 ----
    const float4* xb4 = (const float4*)(x + (long)(2 * b) * NF * ED);
    for (int i = tid; i < 2 * NF * ED / 4; i += NT) {   // 1280 float4
        const float4 v = xb4[i];
        const int row = i >> 4, j = i & 15;             // row in [0,80)
        sx2[row * ST2 + 2 * j]     = pack_h2(v.x, v.y);
        sx2[row * ST2 + 2 * j + 1] = pack_h2(v.z, v.w);
    }

    // ---- stage W1 (fp16 rounded), K-permuted packing ----
    // word w = kk*8 + q*4 + t holds W1[h][e0..e0+1], e0 = kk*16 + 4t + 2q
    for (int i = tid; i < ED * 32; i += NT) {
        const int h = i >> 5, w = i & 31;
        const int kk = w >> 3, q = (w >> 2) & 1, tt = w & 3;
        const int e0 = kk * 16 + 4 * tt + 2 * q;
        sW1h[h][w] = pack_h2(W1[h * 64 + e0], W1[h * 64 + e0 + 1]);
    }
    if (tid < 32) {
        const int n = tid >> 2, tt = tid & 3;
        const int h0 = n * 8 + 2 * tt;
        sEpi[tid] = make_float4(b1[h0], W2[h0], b1[h0 + 1], W2[h0 + 1]);
    }
    if (tid == 0) scal1[0] = bl[0];

    // ---- Wl B-fragment (column 0 only): nonzero in gid==0 lanes ----
    uint32_t wlf[4][2] = {{0u,0u},{0u,0u},{0u,0u},{0u,0u}};
    if (gid == 0 && half == 0) {
        #pragma unroll
        for (int kk = 0; kk < 4; ++kk) {
            const int e = kk * 16 + 4 * t;
            wlf[kk][0] = pack_h2(Wl[e],     Wl[e + 1]);
            wlf[kk][1] = pack_h2(Wl[e + 2], Wl[e + 3]);
        }
    }
    __syncthreads();

    const float blv = scal1[0];

    // ---- load this half's B fragments (32 of 64 W1 rows) ----
    uint32_t bf[4][4][2];
    #pragma unroll
    for (int n = 0; n < 4; ++n) {
        const uint32_t* rowH = sW1h[(half * 4 + n) * 8 + gid];
        #pragma unroll
        for (int kk = 0; kk < 4; ++kk) {
            bf[n][kk][0] = rowH[kk * 8 + t];
            bf[n][kk][1] = rowH[kk * 8 + 4 + t];
        }
    }

    // ---- main loop: 98 tiles over 4 warp-pairs ----
    for (int tile = wp; tile < 2 * NTILE; tile += 4) {
        const int bt = (tile >= NTILE) ? 1 : 0;
        const int p0 = (tile - bt * NTILE) * 16 + gid;
        const int pc0 = p0 < NPAIR ? p0 : NPAIR - 1;
        const int pc1 = (p0 + 8) < NPAIR ? (p0 + 8) : NPAIR - 1;

        const uint32_t* sxb = sx2 + bt * (NF * ST2);
        const uint32_t rc0 = decode_pair(pc0);
        const uint32_t rc1 = decode_pair(pc1);
        const uint32_t* xr0 = sxb + (rc0 >> 8) * ST2 + 2 * t;
        const uint32_t* xc0 = sxb + (rc0 & 255u) * ST2 + 2 * t;
        const uint32_t* xr1 = sxb + (rc1 >> 8) * ST2 + 2 * t;
        const uint32_t* xc1 = sxb + (rc1 & 255u) * ST2 + 2 * t;

        float acc[4][4];
        #pragma unroll
        for (int n = 0; n < 4; ++n)
            acc[n][0] = acc[n][1] = acc[n][2] = acc[n][3] = 0.f;
        float accs[4] = {0.f, 0.f, 0.f, 0.f};

        #pragma unroll
        for (int kk = 0; kk < 4; ++kk) {
            const uint2 a0 = *(const uint2*)(xr0 + kk * 8);
            const uint2 c0 = *(const uint2*)(xc0 + kk * 8);
            const uint2 a1 = *(const uint2*)(xr1 + kk * 8);
            const uint2 c1 = *(const uint2*)(xc1 + kk * 8);

            uint32_t ra[4];
            ra[0] = h2mul(a0.x, c0.x);
            ra[2] = h2mul(a0.y, c0.y);
            ra[1] = h2mul(a1.x, c1.x);
            ra[3] = h2mul(a1.y, c1.y);

            if (half == 0)
                mma16816(accs, ra, wlf[kk][0], wlf[kk][1]);
            #pragma unroll
            for (int n = 0; n < 4; ++n)
                mma16816(acc[n], ra, bf[n][kk][0], bf[n][kk][1]);
        }

        const int ob = bt * NPAD + p0;
        if (half == 0 && t == 0) { svals[ob] = accs[0]; svals[ob + 8] = accs[2]; }

        // ---- fused partial epilogue (this half's 32 hidden cols) ----
        float lg0 = 0.f, lg1 = 0.f;
        #pragma unroll
        for (int n = 0; n < 4; ++n) {
            const float4 ep = sEpi[(half * 4 + n) * 4 + t];
            lg0 = fmaf(fmaxf(acc[n][0] + ep.x, 0.f), ep.y,
                  fmaf(fmaxf(acc[n][1] + ep.z, 0.f), ep.w, lg0));
            lg1 = fmaf(fmaxf(acc[n][2] + ep.x, 0.f), ep.y,
                  fmaf(fmaxf(acc[n][3] + ep.z, 0.f), ep.w, lg1));
        }
        lg0 += __shfl_xor_sync(0xffffffffu, lg0, 1);
        lg0 += __shfl_xor_sync(0xffffffffu, lg0, 2);
        lg1 += __shfl_xor_sync(0xffffffffu, lg1, 1);
        lg1 += __shfl_xor_sync(0xffffffffu, lg1, 2);
        if (t == 0) { lpart[half][ob] = lg0; lpart[half][ob + 8] = lg1; }
    }
    __syncthreads();

    // ---- two independent 4-warp online-softmax reductions ----
    const int group = wid >> 2;     // batch this warp reduces
    const int gw = wid & 3;
    const float* lg0p = lpart[0] + group * NPAD;
    const float* lg1p = lpart[1] + group * NPAD;
    const float* svp  = svals + group * NPAD;

    float m = -FLT_MAX, Z = 0.f, S = 0.f;
    for (int p = gw * 32 + lid; p < NPAIR; p += 128) {
        const float l = lg0p[p] + lg1p[p];
        const float s = svp[p];
        const float mn = fmaxf(m, l);
        const float sc = __expf(m - mn);
        const float w  = __expf(l - mn);
        Z = Z * sc + w;
        S = S * sc + s * w;
        m = mn;
    }
    #pragma unroll
    for (int off = 16; off; off >>= 1) {
        const float m2 = __shfl_down_sync(0xffffffffu, m, off);
        const float Z2 = __shfl_down_sync(0xffffffffu, Z, off);
        const float S2 = __shfl_down_sync(0xffffffffu, S, off);
        const float mn = fmaxf(m, m2);
        const float e1 = __expf(m - mn);
        const float e2 = __expf(m2 - mn);
        Z = Z * e1 + Z2 * e2;
        S = S * e1 + S2 * e2;
        m = mn;
    }
    if (lid == 0) {
        red[group * 12 + gw]     = m;
        red[group * 12 + 4 + gw] = Z;
        red[group * 12 + 8 + gw] = S;
    }
    __syncthreads();
    if (gw == 0) {
        m = (lid < 4) ? red[group * 12 + lid]     : -FLT_MAX;
        Z = (lid < 4) ? red[group * 12 + 4 + lid] : 0.f;
        S = (lid < 4) ? red[group * 12 + 8 + lid] : 0.f;
        #pragma unroll
        for (int off = 2; off; off >>= 1) {
            const float m2 = __shfl_down_sync(0xffffffffu, m, off);
            const float Z2 = __shfl_down_sync(0xffffffffu, Z, off);
            const float S2 = __shfl_down_sync(0xffffffffu, S, off);
            const float mn = fmaxf(m, m2);
            const float e1 = __expf(m - mn);
            const float e2 = __expf(m2 - mn);
            Z = Z * e1 + Z2 * e2;
            S = S * e1 + S2 * e2;
            m = mn;
        }
        if (lid == 0) out[2 * b + group] = S / Z + blv;
    }
}

}  // namespace

extern "C" void kernel_launch(void* const* d_in, const int* in_sizes, int n_in,
                              void* d_out, int out_size)
{
    const float* x  = (const float*)d_in[0];
    const float* W1 = (const float*)d_in[1];
    const float* b1 = (const float*)d_in[2];
    const float* W2 = (const float*)d_in[3];
    const float* b2 = (const float*)d_in[4];
    const float* Wl = (const float*)d_in[5];
    const float* bl = (const float*)d_in[6];
    float* out = (float*)d_out;

    const int batch = in_sizes[0] / (NF * ED);  // 2048
    afm_mma_kernel<<<batch / 2, NT>>>(x, W1, b1, W2, b2, Wl, bl, out);
}

// round 16
// speedup vs baseline: 1.2438x; 1.2438x over previous
#include <cuda_runtime.h>
#include <cuda_fp16.h>
#include <cstdint>
#include <float.h>

// AFM fused kernel — fp16 single-term mma.sync, W1 register-resident,
// fp16 x staging, s_p via extra MMA column, 2 batches/CTA (R12 structure).
// R16: K re-permuted so the x-gather is 8 x LDS.128 per tile (was 16 x
// LDS.64): gather g in {0,1} loads 8 contiguous halves per thread; the 4
// product words feed MMAs kk=2g and kk=2g+1.
//
// out[b] = bl + sum_p softmax_p(l_p) * s_p
//   inner_p = rn16(x[b,r])∘rn16(x[b,c])   (f16x2 products = A fragments)
//   s_p = inner_p·rn16(Wl)                (extra m16n8k16, fp32 accum)
//   l_p = W2·relu(W1·inner_p + b1)        (+b2 dropped: shift-invariant)
//
// K-permutation: MMA kk (g=kk>>1, hs=kk&1): thread t's k-word0 holds
// elements g*32 + 8t + hs*4 + {0,1}, k-word1 holds +{2,3}. W1/Wl packed
// to match; x staged linearly (gather reads are contiguous uint4).

namespace {

constexpr int NF    = 40;
constexpr int ED    = 64;
constexpr int NPAIR = NF * (NF - 1) / 2;   // 780
constexpr int NTILE = (NPAIR + 15) / 16;   // 49
constexpr int NPAD  = NTILE * 16;          // 784
constexpr int NT    = 256;
constexpr int ST2   = 36;                  // sx2 row stride in u32 (half2) words

__device__ __forceinline__ uint32_t pack_h2(float v0, float v1) {
    const __half2 h = __floats2half2_rn(v0, v1);   // .x = v0 (low half)
    return *(const uint32_t*)&h;
}
__device__ __forceinline__ uint32_t h2mul(uint32_t a, uint32_t b) {
    uint32_t d;
    asm("mul.rn.f16x2 %0, %1, %2;" : "=r"(d) : "r"(a), "r"(b));
    return d;
}
__device__ __forceinline__ void mma16816(float* c, uint32_t a0, uint32_t a1,
                                         uint32_t a2, uint32_t a3,
                                         uint32_t b0, uint32_t b1) {
    asm volatile(
        "mma.sync.aligned.m16n8k16.row.col.f32.f16.f16.f32 "
        "{%0,%1,%2,%3}, {%4,%5,%6,%7}, {%8,%9}, {%0,%1,%2,%3};"
        : "+f"(c[0]), "+f"(c[1]), "+f"(c[2]), "+f"(c[3])
        : "r"(a0), "r"(a1), "r"(a2), "r"(a3), "r"(b0), "r"(b1));
}

// pair index p -> (row<<8)|col for upper-triangle k=1, NF=40.
__device__ __forceinline__ uint32_t decode_pair(int p) {
    const float d = sqrtf(6241.0f - 8.0f * (float)p);
    int r = __float2int_rd((79.0f - d) * 0.5f);
    if (r * (79 - r) / 2 > p) --r;
    if ((r + 1) * (78 - r) / 2 <= p) ++r;
    const int c = p - r * (79 - r) / 2 + r + 1;
    return ((uint32_t)r << 8) | (uint32_t)c;
}

__global__ __launch_bounds__(NT, 2)
void afm_mma_kernel(const float* __restrict__ x,
                    const float* __restrict__ W1,
                    const float* __restrict__ b1,
                    const float* __restrict__ W2,
                    const float* __restrict__ b2,
                    const float* __restrict__ Wl,
                    const float* __restrict__ bl,
                    float* __restrict__ out)
{
    __shared__ __align__(16) uint32_t sx2[2 * NF * ST2];  // rows 0-39: b0, 40-79: b1
    __shared__           uint32_t sW1h[ED][36];           // staging for B frag load
    __shared__ __align__(16) float4   sEpi[32];           // (b1,W2,b1,W2) per (n,t)
    __shared__           float    logits[2 * NPAD];
    __shared__           float    svals[2 * NPAD];
    __shared__           float    red[24];
    __shared__           float    scal1[1];

    const int tid = threadIdx.x;
    const int wid = tid >> 5, lid = tid & 31;
    const int gid = lid >> 2, t = lid & 3;
    const int b = blockIdx.x;                 // handles batches 2b, 2b+1

    // ---- stage x for BOTH batches (contiguous in gmem) as half2 ----
    const float4* xb4 = (const float4*)(x + (long)(2 * b) * NF * ED);
    for (int i = tid; i < 2 * NF * ED / 4; i += NT) {   // 1280 float4
        const float4 v = xb4[i];
        const int row = i >> 4, j = i & 15;             // row in [0,80)
        sx2[row * ST2 + 2 * j]     = pack_h2(v.x, v.y);
        sx2[row * ST2 + 2 * j + 1] = pack_h2(v.z, v.w);
    }

    // ---- stage W1 (fp16 rounded), NEW K-permuted packing ----
    // word w = kk*8 + q*4 + t holds W1[h][e0..e0+1],
    // e0 = (kk>>1)*32 + 8t + (kk&1)*4 + 2q
    for (int i = tid; i < ED * 32; i += NT) {
        const int h = i >> 5, w = i & 31;
        const int kk = w >> 3, q = (w >> 2) & 1, tt = w & 3;
        const int e0 = (kk >> 1) * 32 + 8 * tt + (kk & 1) * 4 + 2 * q;
        sW1h[h][w] = pack_h2(W1[h * 64 + e0], W1[h * 64 + e0 + 1]);
    }
    if (tid < 32) {
        const int n = tid >> 2, tt = tid & 3;
        const int h0 = n * 8 + 2 * tt;
        sEpi[tid] = make_float4(b1[h0], W2[h0], b1[h0 + 1], W2[h0 + 1]);
    }
    if (tid == 0) scal1[0] = bl[0];

    // ---- Wl B-fragment (column 0 only), same K-permutation ----
    uint32_t wlf[4][2] = {{0u,0u},{0u,0u},{0u,0u},{0u,0u}};
    if (gid == 0) {
        #pragma unroll
        for (int kk = 0; kk < 4; ++kk) {
            const int e = (kk >> 1) * 32 + 8 * t + (kk & 1) * 4;
            wlf[kk][0] = pack_h2(Wl[e],     Wl[e + 1]);
            wlf[kk][1] = pack_h2(Wl[e + 2], Wl[e + 3]);
        }
    }
    __syncthreads();

    const float blv = scal1[0];

    // ---- load ALL B fragments into registers (whole W1, warp-wide) ----
    uint32_t bf[8][4][2];
    #pragma unroll
    for (int n = 0; n < 8; ++n) {
        const uint32_t* rowH = sW1h[n * 8 + gid];
        #pragma unroll
        for (int kk = 0; kk < 4; ++kk) {
            bf[n][kk][0] = rowH[kk * 8 + t];
            bf[n][kk][1] = rowH[kk * 8 + 4 + t];
        }
    }

    // ---- main loop: 98 tiles (2 batches x 49) over 8 warps ----
    for (int tile = wid; tile < 2 * NTILE; tile += 8) {
        const int bt = (tile >= NTILE) ? 1 : 0;
        const int p0 = (tile - bt * NTILE) * 16 + gid;
        const int pc0 = p0 < NPAIR ? p0 : NPAIR - 1;
        const int pc1 = (p0 + 8) < NPAIR ? (p0 + 8) : NPAIR - 1;

        const uint32_t* sxb = sx2 + bt * (NF * ST2) + 4 * t;
        const uint32_t rc0 = decode_pair(pc0);
        const uint32_t rc1 = decode_pair(pc1);
        const uint32_t* xr0 = sxb + (rc0 >> 8) * ST2;
        const uint32_t* xc0 = sxb + (rc0 & 255u) * ST2;
        const uint32_t* xr1 = sxb + (rc1 >> 8) * ST2;
        const uint32_t* xc1 = sxb + (rc1 & 255u) * ST2;

        float acc[8][4];
        #pragma unroll
        for (int n = 0; n < 8; ++n)
            acc[n][0] = acc[n][1] = acc[n][2] = acc[n][3] = 0.f;
        float accs[4] = {0.f, 0.f, 0.f, 0.f};

        #pragma unroll
        for (int g = 0; g < 2; ++g) {
            // one uint4 per row: 8 contiguous halves (elements g*32+8t..+7)
            const uint4 A0 = *(const uint4*)(xr0 + g * 16);
            const uint4 C0 = *(const uint4*)(xc0 + g * 16);
            const uint4 A1 = *(const uint4*)(xr1 + g * 16);
            const uint4 C1 = *(const uint4*)(xc1 + g * 16);

            // products: p0w0..3 for pair0, p1w0..3 for pair1
            const uint32_t p0w0 = h2mul(A0.x, C0.x);
            const uint32_t p0w1 = h2mul(A0.y, C0.y);
            const uint32_t p0w2 = h2mul(A0.z, C0.z);
            const uint32_t p0w3 = h2mul(A0.w, C0.w);
            const uint32_t p1w0 = h2mul(A1.x, C1.x);
            const uint32_t p1w1 = h2mul(A1.y, C1.y);
            const uint32_t p1w2 = h2mul(A1.z, C1.z);
            const uint32_t p1w3 = h2mul(A1.w, C1.w);

            // MMA kk = 2g : k-words (w0, w1); kk = 2g+1 : (w2, w3)
            const int k0 = 2 * g, k1 = 2 * g + 1;
            mma16816(accs, p0w0, p1w0, p0w1, p1w1, wlf[k0][0], wlf[k0][1]);
            #pragma unroll
            for (int n = 0; n < 8; ++n)
                mma16816(acc[n], p0w0, p1w0, p0w1, p1w1,
                         bf[n][k0][0], bf[n][k0][1]);
            mma16816(accs, p0w2, p1w2, p0w3, p1w3, wlf[k1][0], wlf[k1][1]);
            #pragma unroll
            for (int n = 0; n < 8; ++n)
                mma16816(acc[n], p0w2, p1w2, p0w3, p1w3,
                         bf[n][k1][0], bf[n][k1][1]);
        }

        const int ob = bt * NPAD + p0;
        if (t == 0) { svals[ob] = accs[0]; svals[ob + 8] = accs[2]; }

        // ---- fused epilogue ----
        float lg0 = 0.f, lg1 = 0.f;
        #pragma unroll
        for (int n = 0; n < 8; ++n) {
            const float4 ep = sEpi[n * 4 + t];
            lg0 = fmaf(fmaxf(acc[n][0] + ep.x, 0.f), ep.y,
                  fmaf(fmaxf(acc[n][1] + ep.z, 0.f), ep.w, lg0));
            lg1 = fmaf(fmaxf(acc[n][2] + ep.x, 0.f), ep.y,
                  fmaf(fmaxf(acc[n][3] + ep.z, 0.f), ep.w, lg1));
        }
        lg0 += __shfl_xor_sync(0xffffffffu, lg0, 1);
        lg0 += __shfl_xor_sync(0xffffffffu, lg0, 2);
        lg1 += __shfl_xor_sync(0xffffffffu, lg1, 1);
        lg1 += __shfl_xor_sync(0xffffffffu, lg1, 2);
        if (t == 0) { logits[ob] = lg0; logits[ob + 8] = lg1; }
    }
    __syncthreads();

    // ---- two independent 4-warp online-softmax reductions ----
    const int group = wid >> 2;     // batch this warp reduces
    const int gw = wid & 3;
    const float* lgp = logits + group * NPAD;
    const float* svp = svals + group * NPAD;

    float m = -FLT_MAX, Z = 0.f, S = 0.f;
    for (int p = gw * 32 + lid; p < NPAIR; p += 128) {
        const float l = lgp[p];
        const float s = svp[p];
        const float mn = fmaxf(m, l);
        const float sc = __expf(m - mn);
        const float w  = __expf(l - mn);
        Z = Z * sc + w;
        S = S * sc + s * w;
        m = mn;
    }
    #pragma unroll
    for (int off = 16; off; off >>= 1) {
        const float m2 = __shfl_down_sync(0xffffffffu, m, off);
        const float Z2 = __shfl_down_sync(0xffffffffu, Z, off);
        const float S2 = __shfl_down_sync(0xffffffffu, S, off);
        const float mn = fmaxf(m, m2);
        const float e1 = __expf(m - mn);
        const float e2 = __expf(m2 - mn);
        Z = Z * e1 + Z2 * e2;
        S = S * e1 + S2 * e2;
        m = mn;
    }
    if (lid == 0) {
        red[group * 12 + gw]     = m;
        red[group * 12 + 4 + gw] = Z;
        red[group * 12 + 8 + gw] = S;
    }
    __syncthreads();
    if (gw == 0) {
        m = (lid < 4) ? red[group * 12 + lid]     : -FLT_MAX;
        Z = (lid < 4) ? red[group * 12 + 4 + lid] : 0.f;
        S = (lid < 4) ? red[group * 12 + 8 + lid] : 0.f;
        #pragma unroll
        for (int off = 2; off; off >>= 1) {
            const float m2 = __shfl_down_sync(0xffffffffu, m, off);
            const float Z2 = __shfl_down_sync(0xffffffffu, Z, off);
            const float S2 = __shfl_down_sync(0xffffffffu, S, off);
            const float mn = fmaxf(m, m2);
            const float e1 = __expf(m - mn);
            const float e2 = __expf(m2 - mn);
            Z = Z * e1 + Z2 * e2;
            S = S * e1 + S2 * e2;
            m = mn;
        }
        if (lid == 0) out[2 * b + group] = S / Z + blv;
    }
}

}  // namespace

extern "C" void kernel_launch(void* const* d_in, const int* in_sizes, int n_in,
                              void* d_out, int out_size)
{
    const float* x  = (const float*)d_in[0];
    const float* W1 = (const float*)d_in[1];
    const float* b1 = (const float*)d_in[2];
    const float* W2 = (const float*)d_in[3];
    const float* b2 = (const float*)d_in[4];
    const float* Wl = (const float*)d_in[5];
    const float* bl = (const float*)d_in[6];
    float* out = (float*)d_out;

    const int batch = in_sizes[0] / (NF * ED);  // 2048
    afm_mma_kernel<<<batch / 2, NT>>>(x, W1, b1, W2, b2, Wl, bl, out);
}